// round 11
// baseline (speedup 1.0000x reference)
#include <cuda_runtime.h>
#include <cuda_fp16.h>
#include <cstdint>

// CFConv fused, FP16 mma (m16n8k16). Persistent CTAs; 256-edge tiles; each of
// 4 warps owns 64 edges (mt=4) so one ring step carries 32 mma of work ->
// ring depth 3 now covers DRAM latency in TIME as well as bytes.
// Weights in smem once per CTA; cp.async ring runs across tile boundaries.
//
// h  = softplus_b05(rbf @ W1^T + b1)   [E,128] x [64,128]^T -> [E,64]
// g  = h @ W2^T + b2                   [E,64]  x [64,64]^T  -> [E,64]
// out[dst[e]] += node_feats[src[e]] * g[e]

constexpr int BM      = 256;    // edges per CTA tile
constexpr int THREADS = 128;    // 4 warps x 64 edges

constexpr int W1S  = 68;    // half2 words per W1 row (64 + 4 pad)
constexpr int W2S  = 36;    // half2 words per W2 row (32 + 4 pad)
constexpr int AROW = 20;    // fp32 words per A row (16 + 4 pad)
constexpr int RING = 3;     // chunks in flight per warp

__device__ uint32_t g_W1h[64 * W1S];
__device__ uint32_t g_W2h[64 * W2S];

constexpr int OFF_W1 = 0;
constexpr int OFF_W2 = OFF_W1 + 64 * W1S;        // 4352 words
constexpr int OFF_A  = OFF_W2 + 64 * W2S;        // 6656 words
constexpr int SLOTW  = 64 * AROW;                // 1280 words per ring slot
constexpr int SLOTB  = SLOTW * 4;                // 5120 B
constexpr int AWARP  = RING * SLOTW;             // 3840 words per warp
constexpr int SMEM_WORDS = OFF_A + 4 * AWARP;    // 22016
constexpr int SMEM_BYTES = SMEM_WORDS * 4;       // 88064 -> 2 CTAs/SM

// setup: zero output + convert weights to fp16 padded layout
__global__ void setup_kernel(float4* out4, int n4,
                             const float* __restrict__ W1,
                             const float* __restrict__ W2) {
    int i = blockIdx.x * blockDim.x + threadIdx.x;
    if (i < n4) out4[i] = make_float4(0.f, 0.f, 0.f, 0.f);
    if (i < 64 * W1S) {
        int row = i / W1S, c = i % W1S;
        uint32_t v = 0;
        if (c < 64) {
            __half2 h = __floats2half2_rn(W1[row * 128 + 2 * c], W1[row * 128 + 2 * c + 1]);
            v = *reinterpret_cast<uint32_t*>(&h);
        }
        g_W1h[i] = v;
    }
    if (i < 64 * W2S) {
        int row = i / W2S, c = i % W2S;
        uint32_t v = 0;
        if (c < 32) {
            __half2 h = __floats2half2_rn(W2[row * 64 + 2 * c], W2[row * 64 + 2 * c + 1]);
            v = *reinterpret_cast<uint32_t*>(&h);
        }
        g_W2h[i] = v;
    }
}

__device__ __forceinline__ float softplus_b05(float x) {
    float hx = 0.5f * x;
    return (hx > 14.0f) ? x : 2.0f * __logf(1.0f + __expf(hx));
}

__device__ __forceinline__ uint32_t pack_h2(float lo, float hi) {
    __half2 p = __floats2half2_rn(lo, hi);
    return *reinterpret_cast<uint32_t*>(&p);
}

__device__ __forceinline__ void mma_f16(float c[4], const uint32_t a[4],
                                        uint32_t b0, uint32_t b1) {
    asm volatile(
        "mma.sync.aligned.m16n8k16.row.col.f32.f16.f16.f32 "
        "{%0,%1,%2,%3}, {%4,%5,%6,%7}, {%8,%9}, {%0,%1,%2,%3};"
        : "+f"(c[0]), "+f"(c[1]), "+f"(c[2]), "+f"(c[3])
        : "r"(a[0]), "r"(a[1]), "r"(a[2]), "r"(a[3]), "r"(b0), "r"(b1));
}

__device__ __forceinline__ void ldsm_x4(uint32_t r[4], uint32_t addr) {
    asm volatile("ldmatrix.sync.aligned.m8n8.x4.shared.b16 {%0,%1,%2,%3}, [%4];"
                 : "=r"(r[0]), "=r"(r[1]), "=r"(r[2]), "=r"(r[3]) : "r"(addr));
}

__device__ __forceinline__ void cp_async16(uint32_t saddr, const void* gsrc) {
    asm volatile("cp.async.cg.shared.global [%0], [%1], 16;"
                 :: "r"(saddr), "l"(gsrc));
}

__device__ __forceinline__ float2 lds_f2(uint32_t addr) {
    float2 v;
    asm volatile("ld.shared.v2.f32 {%0,%1}, [%2];"
                 : "=f"(v.x), "=f"(v.y) : "r"(addr));
    return v;
}

__global__ void __launch_bounds__(THREADS, 2) cfconv_f16_kernel(
    const float* __restrict__ rbf,   // [E,128]
    const float* __restrict__ nf,    // [N,64]
    const int*   __restrict__ src,   // [E]
    const int*   __restrict__ dst,   // [E]
    const float* __restrict__ b1,    // [64]
    const float* __restrict__ b2,    // [64]
    float*       __restrict__ out,   // [N,64]
    int E, int ntiles)
{
    extern __shared__ uint32_t smem[];

    const int tid  = threadIdx.x;
    const int lane = tid & 31;
    const int warp = tid >> 5;
    const int gr   = lane >> 2;
    const int gc   = lane & 3;
    const int wrow = warp * 64;            // warp's 64 edges within tile
    const unsigned FULL = 0xffffffffu;
    const bool odd = (gc & 1);
    const char* rbfB = (const char*)rbf;

    const uint32_t sbase = (uint32_t)__cvta_generic_to_shared(smem);

    // ---- group 0: weights, loaded ONCE per persistent CTA ----
    for (int i = tid; i < 1088; i += THREADS)
        cp_async16(sbase + OFF_W1 * 4 + i * 16, (const char*)g_W1h + i * 16);
    for (int i = tid; i < 576; i += THREADS)
        cp_async16(sbase + OFF_W2 * 4 + i * 16, (const char*)g_W2h + i * 16);
    asm volatile("cp.async.commit_group;");

    // ---- ring geometry: lane covers rows (lane>>2)+8i (i=0..7), 16B each ----
    const uint32_t aBase = sbase + (OFF_A + warp * AWARP) * 4;
    const int lrow = lane >> 2;
    // smem store base; row i at uniform stride 8*AROW*4 = 640B
    const uint32_t sdst0 = aBase + (lrow * AROW + (lane & 3) * 4) * 4;

    // ---- B-fragment ldsm addresses ----
    const int lb = ((lane >> 4) << 3) | (lane & 7);
    const int sbyt = ((lane >> 3) & 1) * 16;
    uint32_t bW1a[4], bW2a[4];
    #pragma unroll
    for (int p = 0; p < 4; p++) {
        bW1a[p] = sbase + (OFF_W1 + (p * 16 + lb) * W1S) * 4 + sbyt;
        bW2a[p] = sbase + (OFF_W2 + (p * 16 + lb) * W2S) * 4 + sbyt;
    }

    // ---- first tile's rbf byte-offsets (32-bit; rbf area < 4GB) ----
    int tile = blockIdx.x;
    const int gstride = gridDim.x;
    uint32_t offN[8];
    #pragma unroll
    for (int i = 0; i < 8; i++) {
        long e = (long)tile * BM + wrow + lrow + 8 * i;
        long ec = (e < E) ? e : 0;
        offN[i] = (uint32_t)(ec * 512) + (lane & 3) * 16;
    }
    // prime ring with chunks 0..2 of first tile
    #pragma unroll
    for (int c = 0; c < RING; c++) {
        #pragma unroll
        for (int i = 0; i < 8; i++)
            cp_async16(sdst0 + c * SLOTB + i * 640, rbfB + offN[i] + c * 64);
        asm volatile("cp.async.commit_group;");
    }

    asm volatile("cp.async.wait_group 3;");   // own weight parts done
    __syncthreads();                          // weights visible block-wide

    int slot = 0;   // ring slot of next chunk to consume (8 % 3 != 0 -> runtime)

    for (; tile < ntiles; tile += gstride) {
        uint32_t offC[8];
        #pragma unroll
        for (int i = 0; i < 8; i++) offC[i] = offN[i];
        {
            int tnext = tile + gstride;
            int tsrc = (tnext < ntiles) ? tnext : tile;   // phantom reload on last
            #pragma unroll
            for (int i = 0; i < 8; i++) {
                long e = (long)tsrc * BM + wrow + lrow + 8 * i;
                long ec = (e < E) ? e : 0;
                offN[i] = (uint32_t)(ec * 512) + (lane & 3) * 16;
            }
        }

        // lane-private edge indices: rows wrow+lane and wrow+32+lane
        const long eM0 = (long)tile * BM + wrow + lane;
        const long eM1 = eM0 + 32;
        int myS0 = (eM0 < E) ? src[eM0] : 0;
        int myD0 = (eM0 < E) ? dst[eM0] : 0;
        int myS1 = (eM1 < E) ? src[eM1] : 0;
        int myD1 = (eM1 < E) ? dst[eM1] : 0;

        // ---- GEMM1: 8 chunks of 16; replacement chunk issued each step ----
        float acc[4][8][4] = {};
        #pragma unroll
        for (int c = 0; c < 8; c++) {
            asm volatile("cp.async.wait_group 2;");
            __syncwarp();
            const uint32_t bo = slot * SLOTB;

            uint32_t a[4][4];
            #pragma unroll
            for (int mt = 0; mt < 4; mt++) {
                const uint32_t r0 = aBase + bo + ((mt * 16 + gr) * AROW + 2 * gc) * 4;
                const uint32_t r1 = r0 + 8 * AROW * 4;
                float2 f0 = lds_f2(r0);
                float2 f1 = lds_f2(r1);
                float2 f2 = lds_f2(r0 + 32);
                float2 f3 = lds_f2(r1 + 32);
                a[mt][0] = pack_h2(f0.x, f0.y);
                a[mt][1] = pack_h2(f1.x, f1.y);
                a[mt][2] = pack_h2(f2.x, f2.y);
                a[mt][3] = pack_h2(f3.x, f3.y);
            }

            __syncwarp();   // frags in registers: slot reusable
            {
                const uint32_t* off = (c + RING < 8) ? offC : offN;  // c compile-time
                const int cc = (c + RING) & 7;
                #pragma unroll
                for (int i = 0; i < 8; i++)
                    cp_async16(sdst0 + bo + i * 640, rbfB + off[i] + cc * 64);
                asm volatile("cp.async.commit_group;");
            }
            slot = (slot == RING - 1) ? 0 : slot + 1;

            #pragma unroll
            for (int p = 0; p < 4; p++) {
                uint32_t bb[4];
                ldsm_x4(bb, bW1a[p] + c * 32);
                #pragma unroll
                for (int mt = 0; mt < 4; mt++) {
                    mma_f16(acc[mt][2 * p],     a[mt], bb[0], bb[1]);
                    mma_f16(acc[mt][2 * p + 1], a[mt], bb[2], bb[3]);
                }
            }
        }

        // ---- bias + softplus + pack: GEMM1 C-frags -> GEMM2 A-frags ----
        uint32_t hA[4][4][4];
        #pragma unroll
        for (int kt = 0; kt < 4; kt++) {
            float bA0 = __ldg(b1 + kt * 16 + 2 * gc);
            float bA1 = __ldg(b1 + kt * 16 + 2 * gc + 1);
            float bB0 = __ldg(b1 + kt * 16 + 8 + 2 * gc);
            float bB1 = __ldg(b1 + kt * 16 + 8 + 2 * gc + 1);
            #pragma unroll
            for (int mt = 0; mt < 4; mt++) {
                const float* cA = acc[mt][2 * kt];
                const float* cB = acc[mt][2 * kt + 1];
                hA[mt][kt][0] = pack_h2(softplus_b05(cA[0] + bA0), softplus_b05(cA[1] + bA1));
                hA[mt][kt][1] = pack_h2(softplus_b05(cA[2] + bA0), softplus_b05(cA[3] + bA1));
                hA[mt][kt][2] = pack_h2(softplus_b05(cB[0] + bB0), softplus_b05(cB[1] + bB1));
                hA[mt][kt][3] = pack_h2(softplus_b05(cB[2] + bB0), softplus_b05(cB[3] + bB1));
            }
        }

        // ---- GEMM2: K=64, 4 chunks of 16 ----
        float acc2[4][8][4] = {};
        #pragma unroll
        for (int kt = 0; kt < 4; kt++) {
            #pragma unroll
            for (int p = 0; p < 4; p++) {
                uint32_t bb[4];
                ldsm_x4(bb, bW2a[p] + kt * 32);
                #pragma unroll
                for (int mt = 0; mt < 4; mt++) {
                    mma_f16(acc2[mt][2 * p],     hA[mt][kt], bb[0], bb[1]);
                    mma_f16(acc2[mt][2 * p + 1], hA[mt][kt], bb[2], bb[3]);
                }
            }
        }

        // ---- epilogue (overlaps next tile's ring fills): gate + scatter ----
        #pragma unroll
        for (int mt = 0; mt < 4; mt++) {
            int rowl = mt * 16 + gr + (odd ? 8 : 0);         // 0..63
            int s = (mt < 2) ? __shfl_sync(FULL, myS0, rowl)
                             : __shfl_sync(FULL, myS1, rowl - 32);
            int d = (mt < 2) ? __shfl_sync(FULL, myD0, rowl)
                             : __shfl_sync(FULL, myD1, rowl - 32);
            bool valid = ((long)tile * BM + wrow + rowl < E);
            const float* nfr = nf + (long)s * 64;
            float* outr = out + (long)d * 64;
            #pragma unroll
            for (int nt = 0; nt < 8; nt++) {
                float bc0 = __ldg(b2 + nt * 8 + 2 * gc);
                float bc1 = __ldg(b2 + nt * 8 + 2 * gc + 1);
                float g0 = acc2[mt][nt][0] + bc0, g1 = acc2[mt][nt][1] + bc1;
                float g2 = acc2[mt][nt][2] + bc0, g3 = acc2[mt][nt][3] + bc1;
                float x0 = __shfl_xor_sync(FULL, g0, 1);
                float x1 = __shfl_xor_sync(FULL, g1, 1);
                float x2 = __shfl_xor_sync(FULL, g2, 1);
                float x3 = __shfl_xor_sync(FULL, g3, 1);
                float v0, v1, v2, v3;
                if (odd) { v0 = x2; v1 = x3; v2 = g2; v3 = g3; }
                else     { v0 = g0; v1 = g1; v2 = x0; v3 = x1; }
                int col = nt * 8 + 4 * (gc >> 1);
                if (valid) {
                    float4 nf4 = *(const float4*)(nfr + col);
                    v0 *= nf4.x; v1 *= nf4.y; v2 *= nf4.z; v3 *= nf4.w;
                    asm volatile("red.global.add.v4.f32 [%0], {%1,%2,%3,%4};"
                                 :: "l"(outr + col), "f"(v0), "f"(v1), "f"(v2), "f"(v3)
                                 : "memory");
                }
            }
        }
    }
}

extern "C" void kernel_launch(void* const* d_in, const int* in_sizes, int n_in,
                              void* d_out, int out_size) {
    const float* rbf = (const float*)d_in[0];
    const float* nf  = (const float*)d_in[1];
    const int*   src = (const int*)d_in[2];
    const int*   dst = (const int*)d_in[3];
    const float* W1  = (const float*)d_in[4];
    const float* b1  = (const float*)d_in[5];
    const float* W2  = (const float*)d_in[6];
    const float* b2  = (const float*)d_in[7];
    float* out = (float*)d_out;

    const int E = in_sizes[2];
    const int ntiles = (E + BM - 1) / BM;

    cudaFuncSetAttribute(cfconv_f16_kernel,
                         cudaFuncAttributeMaxDynamicSharedMemorySize, SMEM_BYTES);

    int n4 = out_size / 4;
    setup_kernel<<<(n4 + 255) / 256, 256>>>((float4*)out, n4, W1, W2);

    int grid = 148 * 2;
    if (grid > ntiles) grid = ntiles;
    cfconv_f16_kernel<<<grid, THREADS, SMEM_BYTES>>>(
        rbf, nf, src, dst, b1, b2, out, E, ntiles);
}

// round 13
// speedup vs baseline: 1.0231x; 1.0231x over previous
#include <cuda_runtime.h>
#include <cuda_fp16.h>
#include <cstdint>

// CFConv fused, FP16 mma (m16n8k16), WARP-SPECIALIZED:
//   warps 0-3: consumers (mma + softplus + epilogue), never issue gmem loads
//   warps 4-5: producers, stream rbf chunks into an 8-stage mbarrier ring
// Persistent CTAs; weights in smem once; producers run ahead across tiles.
// R11 deadlock fix: cp.async.mbarrier.arrive must be .noinc (default form is
// count-neutral: +1 pending then arrive, so a count-64 barrier never fired).
//
// h  = softplus_b05(rbf @ W1^T + b1)   [E,128] x [64,128]^T -> [E,64]
// g  = h @ W2^T + b2                   [E,64]  x [64,64]^T  -> [E,64]
// out[dst[e]] += node_feats[src[e]] * g[e]

constexpr int BM      = 128;    // edges per tile
constexpr int THREADS = 192;    // 4 consumer warps + 2 producer warps
constexpr int DEPTH   = 8;      // ring stages == chunks per tile (parity/tile)

constexpr int W1S  = 68;    // half2 words per W1 row (64 + 4 pad)
constexpr int W2S  = 36;    // half2 words per W2 row (32 + 4 pad)
constexpr int AROW = 20;    // fp32 words per stage row (16 + 4 pad)

__device__ uint32_t g_W1h[64 * W1S];
__device__ uint32_t g_W2h[64 * W2S];

constexpr int OFF_W1  = 0;
constexpr int OFF_W2  = OFF_W1 + 64 * W1S;         // 4352 words
constexpr int OFF_STG = OFF_W2 + 64 * W2S;         // 6656 words
constexpr int STGW    = BM * AROW;                 // 2560 words per stage (10240B)
constexpr int OFF_MB  = OFF_STG + DEPTH * STGW;    // 27136 words
constexpr int SMEM_WORDS = OFF_MB + DEPTH * 4;     // full/empty pairs, 16B/stage
constexpr int SMEM_BYTES = SMEM_WORDS * 4;         // 108672 -> 2 CTAs/SM

// setup: zero output + convert weights to fp16 padded layout
__global__ void setup_kernel(float4* out4, int n4,
                             const float* __restrict__ W1,
                             const float* __restrict__ W2) {
    int i = blockIdx.x * blockDim.x + threadIdx.x;
    if (i < n4) out4[i] = make_float4(0.f, 0.f, 0.f, 0.f);
    if (i < 64 * W1S) {
        int row = i / W1S, c = i % W1S;
        uint32_t v = 0;
        if (c < 64) {
            __half2 h = __floats2half2_rn(W1[row * 128 + 2 * c], W1[row * 128 + 2 * c + 1]);
            v = *reinterpret_cast<uint32_t*>(&h);
        }
        g_W1h[i] = v;
    }
    if (i < 64 * W2S) {
        int row = i / W2S, c = i % W2S;
        uint32_t v = 0;
        if (c < 32) {
            __half2 h = __floats2half2_rn(W2[row * 64 + 2 * c], W2[row * 64 + 2 * c + 1]);
            v = *reinterpret_cast<uint32_t*>(&h);
        }
        g_W2h[i] = v;
    }
}

__device__ __forceinline__ float softplus_b05(float x) {
    float hx = 0.5f * x;
    return (hx > 14.0f) ? x : 2.0f * __logf(1.0f + __expf(hx));
}

__device__ __forceinline__ uint32_t pack_h2(float lo, float hi) {
    __half2 p = __floats2half2_rn(lo, hi);
    return *reinterpret_cast<uint32_t*>(&p);
}

__device__ __forceinline__ void mma_f16(float c[4], const uint32_t a[4],
                                        uint32_t b0, uint32_t b1) {
    asm volatile(
        "mma.sync.aligned.m16n8k16.row.col.f32.f16.f16.f32 "
        "{%0,%1,%2,%3}, {%4,%5,%6,%7}, {%8,%9}, {%0,%1,%2,%3};"
        : "+f"(c[0]), "+f"(c[1]), "+f"(c[2]), "+f"(c[3])
        : "r"(a[0]), "r"(a[1]), "r"(a[2]), "r"(a[3]), "r"(b0), "r"(b1));
}

__device__ __forceinline__ void ldsm_x4(uint32_t r[4], uint32_t addr) {
    asm volatile("ldmatrix.sync.aligned.m8n8.x4.shared.b16 {%0,%1,%2,%3}, [%4];"
                 : "=r"(r[0]), "=r"(r[1]), "=r"(r[2]), "=r"(r[3]) : "r"(addr));
}

__device__ __forceinline__ void cp_async16(uint32_t saddr, const void* gsrc) {
    asm volatile("cp.async.cg.shared.global [%0], [%1], 16;"
                 :: "r"(saddr), "l"(gsrc));
}

__device__ __forceinline__ float2 lds_f2(uint32_t addr) {
    float2 v;
    asm volatile("ld.shared.v2.f32 {%0,%1}, [%2];"
                 : "=f"(v.x), "=f"(v.y) : "r"(addr));
    return v;
}

__device__ __forceinline__ void mbar_init(uint32_t addr, uint32_t count) {
    asm volatile("mbarrier.init.shared.b64 [%0], %1;" :: "r"(addr), "r"(count) : "memory");
}
__device__ __forceinline__ void mbar_arrive(uint32_t addr) {
    asm volatile("mbarrier.arrive.shared.b64 _, [%0];" :: "r"(addr) : "memory");
}
__device__ __forceinline__ void cp_async_mbar_arrive_noinc(uint32_t addr) {
    asm volatile("cp.async.mbarrier.arrive.noinc.shared.b64 [%0];" :: "r"(addr) : "memory");
}
__device__ __forceinline__ void mbar_wait(uint32_t addr, uint32_t parity) {
    asm volatile(
        "{\n\t.reg .pred P;\n\t"
        "WAIT_%=:\n\t"
        "mbarrier.try_wait.parity.acquire.cta.shared::cta.b64 P, [%0], %1, 0x989680;\n\t"
        "@P bra.uni DONE_%=;\n\t"
        "bra.uni WAIT_%=;\n\t"
        "DONE_%=:\n\t}"
        :: "r"(addr), "r"(parity) : "memory");
}

__global__ void __launch_bounds__(THREADS, 2) cfconv_f16_kernel(
    const float* __restrict__ rbf,   // [E,128]
    const float* __restrict__ nf,    // [N,64]
    const int*   __restrict__ src,   // [E]
    const int*   __restrict__ dst,   // [E]
    const float* __restrict__ b1,    // [64]
    const float* __restrict__ b2,    // [64]
    float*       __restrict__ out,   // [N,64]
    int E, int ntiles)
{
    extern __shared__ uint32_t smem[];

    const int tid  = threadIdx.x;
    const int lane = tid & 31;
    const int warp = tid >> 5;
    const int gstride = gridDim.x;
    const unsigned FULL = 0xffffffffu;
    const char* rbfB = (const char*)rbf;

    const uint32_t sbase = (uint32_t)__cvta_generic_to_shared(smem);
    const uint32_t stg0  = sbase + OFF_STG * 4;
    const uint32_t mb0   = sbase + OFF_MB * 4;
    // full[c] at mb0 + c*16, empty[c] at mb0 + c*16 + 8

    // ---- weights via cp.async (all warps help), mbarrier init ----
    for (int i = tid; i < 1088; i += THREADS)
        cp_async16(sbase + OFF_W1 * 4 + i * 16, (const char*)g_W1h + i * 16);
    for (int i = tid; i < 576; i += THREADS)
        cp_async16(sbase + OFF_W2 * 4 + i * 16, (const char*)g_W2h + i * 16);
    asm volatile("cp.async.commit_group;");
    if (tid < DEPTH) {
        mbar_init(mb0 + tid * 16,     64);  // full: 64 producer-thread completions
        mbar_init(mb0 + tid * 16 + 8, 4);   // empty: 4 consumer warps
    }
    asm volatile("cp.async.wait_group 0;");
    __syncthreads();   // weights + mbarriers visible

    if (warp >= 4) {
        // ===================== PRODUCER (warps 4,5; 64 threads) ===============
        const int pt   = tid - 128;        // 0..63
        const int prow = pt >> 2;          // 0..15
        const int pcol = pt & 3;           // 16B column
        int pphase = 0;                    // consumers pre-arrive -> phase 0 done
        for (int tile = blockIdx.x; tile < ntiles; tile += gstride) {
            // clamped row byte-offsets for this tile (rows prow+16i)
            uint32_t roff[8];
            #pragma unroll
            for (int i = 0; i < 8; i++) {
                long e = (long)tile * BM + prow + 16 * i;
                long ec = (e < E) ? e : 0;
                roff[i] = (uint32_t)(ec * 512) + pcol * 16;
            }
            #pragma unroll
            for (int c = 0; c < 8; c++) {
                mbar_wait(mb0 + c * 16 + 8, pphase);   // stage free?
                const uint32_t sb = stg0 + c * STGW * 4 + (prow * AROW + pcol * 4) * 4;
                #pragma unroll
                for (int i = 0; i < 8; i++)
                    cp_async16(sb + i * 16 * AROW * 4, rbfB + roff[i] + c * 64);
                cp_async_mbar_arrive_noinc(mb0 + c * 16);  // fire full[c] on completion
            }
            pphase ^= 1;
        }
    } else {
        // ===================== CONSUMER (warps 0-3) ==========================
        const int gr   = lane >> 2;
        const int gc   = lane & 3;
        const int wrow = warp * 32;
        const bool odd = (gc & 1);

        // pre-arrive all empties once: completes empty phase 0
        if (lane == 0) {
            #pragma unroll
            for (int c = 0; c < 8; c++) mbar_arrive(mb0 + c * 16 + 8);
        }

        // B-fragment ldsm addresses
        const int lb = ((lane >> 4) << 3) | (lane & 7);
        const int sbyt = ((lane >> 3) & 1) * 16;
        uint32_t bW1a[4], bW2a[4];
        #pragma unroll
        for (int p = 0; p < 4; p++) {
            bW1a[p] = sbase + (OFF_W1 + (p * 16 + lb) * W1S) * 4 + sbyt;
            bW2a[p] = sbase + (OFF_W2 + (p * 16 + lb) * W2S) * 4 + sbyt;
        }

        int cphase = 0;
        for (int tile = blockIdx.x; tile < ntiles; tile += gstride) {
            const long eMine = (long)tile * BM + wrow + lane;
            const bool valMine = (eMine < E);
            int myS = valMine ? src[eMine] : 0;
            int myD = valMine ? dst[eMine] : 0;

            // ---- GEMM1: 8 stages of K=16 ----
            float acc[2][8][4] = {};
            #pragma unroll
            for (int c = 0; c < 8; c++) {
                mbar_wait(mb0 + c * 16, cphase);       // stage filled?
                const uint32_t sb = stg0 + c * STGW * 4;

                uint32_t a[2][4];
                #pragma unroll
                for (int mt = 0; mt < 2; mt++) {
                    const uint32_t r0 = sb + ((wrow + mt * 16 + gr) * AROW + 2 * gc) * 4;
                    const uint32_t r1 = r0 + 8 * AROW * 4;
                    float2 f0 = lds_f2(r0);
                    float2 f1 = lds_f2(r1);
                    float2 f2 = lds_f2(r0 + 32);
                    float2 f3 = lds_f2(r1 + 32);
                    a[mt][0] = pack_h2(f0.x, f0.y);
                    a[mt][1] = pack_h2(f1.x, f1.y);
                    a[mt][2] = pack_h2(f2.x, f2.y);
                    a[mt][3] = pack_h2(f3.x, f3.y);
                }
                __syncwarp();                           // all lanes done reading
                if (lane == 0) mbar_arrive(mb0 + c * 16 + 8);   // release stage

                #pragma unroll
                for (int p = 0; p < 4; p++) {
                    uint32_t bb[4];
                    ldsm_x4(bb, bW1a[p] + c * 32);
                    mma_f16(acc[0][2 * p],     a[0], bb[0], bb[1]);
                    mma_f16(acc[1][2 * p],     a[1], bb[0], bb[1]);
                    mma_f16(acc[0][2 * p + 1], a[0], bb[2], bb[3]);
                    mma_f16(acc[1][2 * p + 1], a[1], bb[2], bb[3]);
                }
            }
            cphase ^= 1;

            // ---- bias + softplus + pack: C-frags -> GEMM2 A-frags ----
            uint32_t hA[2][4][4];
            #pragma unroll
            for (int kt = 0; kt < 4; kt++) {
                float bA0 = __ldg(b1 + kt * 16 + 2 * gc);
                float bA1 = __ldg(b1 + kt * 16 + 2 * gc + 1);
                float bB0 = __ldg(b1 + kt * 16 + 8 + 2 * gc);
                float bB1 = __ldg(b1 + kt * 16 + 8 + 2 * gc + 1);
                #pragma unroll
                for (int mt = 0; mt < 2; mt++) {
                    const float* cA = acc[mt][2 * kt];
                    const float* cB = acc[mt][2 * kt + 1];
                    hA[mt][kt][0] = pack_h2(softplus_b05(cA[0] + bA0), softplus_b05(cA[1] + bA1));
                    hA[mt][kt][1] = pack_h2(softplus_b05(cA[2] + bA0), softplus_b05(cA[3] + bA1));
                    hA[mt][kt][2] = pack_h2(softplus_b05(cB[0] + bB0), softplus_b05(cB[1] + bB1));
                    hA[mt][kt][3] = pack_h2(softplus_b05(cB[2] + bB0), softplus_b05(cB[3] + bB1));
                }
            }

            // ---- GEMM2: K=64, 4 chunks of 16 ----
            float acc2[2][8][4] = {};
            #pragma unroll
            for (int kt = 0; kt < 4; kt++) {
                #pragma unroll
                for (int p = 0; p < 4; p++) {
                    uint32_t bb[4];
                    ldsm_x4(bb, bW2a[p] + kt * 32);
                    mma_f16(acc2[0][2 * p],     hA[0][kt], bb[0], bb[1]);
                    mma_f16(acc2[1][2 * p],     hA[1][kt], bb[0], bb[1]);
                    mma_f16(acc2[0][2 * p + 1], hA[0][kt], bb[2], bb[3]);
                    mma_f16(acc2[1][2 * p + 1], hA[1][kt], bb[2], bb[3]);
                }
            }

            // ---- epilogue: gate by nf[src], vector red scatter (producers keep
            //      filling the ring meanwhile) ----
            #pragma unroll
            for (int mt = 0; mt < 2; mt++) {
                int rowl = mt * 16 + gr + (odd ? 8 : 0);
                int s = __shfl_sync(FULL, myS, rowl);
                int d = __shfl_sync(FULL, myD, rowl);
                bool valid = ((long)tile * BM + wrow + rowl < E);
                const float* nfr = nf + (long)s * 64;
                float* outr = out + (long)d * 64;
                #pragma unroll
                for (int nt = 0; nt < 8; nt++) {
                    float bc0 = __ldg(b2 + nt * 8 + 2 * gc);
                    float bc1 = __ldg(b2 + nt * 8 + 2 * gc + 1);
                    float g0 = acc2[mt][nt][0] + bc0, g1 = acc2[mt][nt][1] + bc1;
                    float g2 = acc2[mt][nt][2] + bc0, g3 = acc2[mt][nt][3] + bc1;
                    float x0 = __shfl_xor_sync(FULL, g0, 1);
                    float x1 = __shfl_xor_sync(FULL, g1, 1);
                    float x2 = __shfl_xor_sync(FULL, g2, 1);
                    float x3 = __shfl_xor_sync(FULL, g3, 1);
                    float v0, v1, v2, v3;
                    if (odd) { v0 = x2; v1 = x3; v2 = g2; v3 = g3; }
                    else     { v0 = g0; v1 = g1; v2 = x0; v3 = x1; }
                    int col = nt * 8 + 4 * (gc >> 1);
                    if (valid) {
                        float4 nf4 = *(const float4*)(nfr + col);
                        v0 *= nf4.x; v1 *= nf4.y; v2 *= nf4.z; v3 *= nf4.w;
                        asm volatile("red.global.add.v4.f32 [%0], {%1,%2,%3,%4};"
                                     :: "l"(outr + col), "f"(v0), "f"(v1), "f"(v2), "f"(v3)
                                     : "memory");
                    }
                }
            }
        }
    }
}

extern "C" void kernel_launch(void* const* d_in, const int* in_sizes, int n_in,
                              void* d_out, int out_size) {
    const float* rbf = (const float*)d_in[0];
    const float* nf  = (const float*)d_in[1];
    const int*   src = (const int*)d_in[2];
    const int*   dst = (const int*)d_in[3];
    const float* W1  = (const float*)d_in[4];
    const float* b1  = (const float*)d_in[5];
    const float* W2  = (const float*)d_in[6];
    const float* b2  = (const float*)d_in[7];
    float* out = (float*)d_out;

    const int E = in_sizes[2];
    const int ntiles = (E + BM - 1) / BM;

    cudaFuncSetAttribute(cfconv_f16_kernel,
                         cudaFuncAttributeMaxDynamicSharedMemorySize, SMEM_BYTES);

    int n4 = out_size / 4;
    setup_kernel<<<(n4 + 255) / 256, 256>>>((float4*)out, n4, W1, W2);

    int grid = 148 * 2;
    if (grid > ntiles) grid = ntiles;
    cfconv_f16_kernel<<<grid, THREADS, SMEM_BYTES>>>(
        rbf, nf, src, dst, b1, b2, out, E, ntiles);
}

// round 14
// speedup vs baseline: 1.0385x; 1.0151x over previous
#include <cuda_runtime.h>
#include <cuda_fp16.h>
#include <cstdint>

// CFConv fused, FP16 mma (m16n8k16). A-operand (rbf) loaded DIRECTLY from
// gmem into registers in the mma fragment pattern (sector-coalesced LDG.64),
// depth-4 rolling register buffer -> no smem staging, no wait_group convoys;
// latency hidden by per-register scoreboard + cross-tile prefetch.
// Persistent CTAs; weights in smem once per CTA.
//
// h  = softplus_b05(rbf @ W1^T + b1)   [E,128] x [64,128]^T -> [E,64]
// g  = h @ W2^T + b2                   [E,64]  x [64,64]^T  -> [E,64]
// out[dst[e]] += node_feats[src[e]] * g[e]

constexpr int BM      = 128;    // edges per tile
constexpr int THREADS = 128;    // 4 warps x 32 edges

constexpr int W1S = 68;     // half2 words per W1 row (64 + 4 pad) -> ldsm conflict-free
constexpr int W2S = 36;     // half2 words per W2 row (32 + 4 pad)

__device__ uint32_t g_W1h[64 * W1S];
__device__ uint32_t g_W2h[64 * W2S];

constexpr int OFF_W1 = 0;
constexpr int OFF_W2 = OFF_W1 + 64 * W1S;      // 4352 words
constexpr int SMEM_WORDS = OFF_W2 + 64 * W2S;  // 6656 words
constexpr int SMEM_BYTES = SMEM_WORDS * 4;     // 26624 B (weights only)

// setup: zero output + convert weights to fp16 padded layout
__global__ void setup_kernel(float4* out4, int n4,
                             const float* __restrict__ W1,
                             const float* __restrict__ W2) {
    int i = blockIdx.x * blockDim.x + threadIdx.x;
    if (i < n4) out4[i] = make_float4(0.f, 0.f, 0.f, 0.f);
    if (i < 64 * W1S) {
        int row = i / W1S, c = i % W1S;
        uint32_t v = 0;
        if (c < 64) {
            __half2 h = __floats2half2_rn(W1[row * 128 + 2 * c], W1[row * 128 + 2 * c + 1]);
            v = *reinterpret_cast<uint32_t*>(&h);
        }
        g_W1h[i] = v;
    }
    if (i < 64 * W2S) {
        int row = i / W2S, c = i % W2S;
        uint32_t v = 0;
        if (c < 32) {
            __half2 h = __floats2half2_rn(W2[row * 64 + 2 * c], W2[row * 64 + 2 * c + 1]);
            v = *reinterpret_cast<uint32_t*>(&h);
        }
        g_W2h[i] = v;
    }
}

__device__ __forceinline__ float softplus_b05(float x) {
    float hx = 0.5f * x;
    return (hx > 14.0f) ? x : 2.0f * __logf(1.0f + __expf(hx));
}

__device__ __forceinline__ uint32_t pack_h2(float2 v) {
    __half2 p = __floats2half2_rn(v.x, v.y);
    return *reinterpret_cast<uint32_t*>(&p);
}
__device__ __forceinline__ uint32_t pack_h2f(float lo, float hi) {
    __half2 p = __floats2half2_rn(lo, hi);
    return *reinterpret_cast<uint32_t*>(&p);
}

__device__ __forceinline__ void mma_f16(float c[4], const uint32_t a[4],
                                        uint32_t b0, uint32_t b1) {
    asm volatile(
        "mma.sync.aligned.m16n8k16.row.col.f32.f16.f16.f32 "
        "{%0,%1,%2,%3}, {%4,%5,%6,%7}, {%8,%9}, {%0,%1,%2,%3};"
        : "+f"(c[0]), "+f"(c[1]), "+f"(c[2]), "+f"(c[3])
        : "r"(a[0]), "r"(a[1]), "r"(a[2]), "r"(a[3]), "r"(b0), "r"(b1));
}

__device__ __forceinline__ void ldsm_x4(uint32_t r[4], uint32_t addr) {
    asm volatile("ldmatrix.sync.aligned.m8n8.x4.shared.b16 {%0,%1,%2,%3}, [%4];"
                 : "=r"(r[0]), "=r"(r[1]), "=r"(r[2]), "=r"(r[3]) : "r"(addr));
}

__device__ __forceinline__ void cp_async16(uint32_t saddr, const void* gsrc) {
    asm volatile("cp.async.cg.shared.global [%0], [%1], 16;"
                 :: "r"(saddr), "l"(gsrc));
}

__device__ __forceinline__ float2 ldg_f2(const char* p) {
    float2 v;
    asm volatile("ld.global.v2.f32 {%0,%1}, [%2];" : "=f"(v.x), "=f"(v.y) : "l"(p));
    return v;
}

__global__ void __launch_bounds__(THREADS, 2) cfconv_f16_kernel(
    const float* __restrict__ rbf,   // [E,128]
    const float* __restrict__ nf,    // [N,64]
    const int*   __restrict__ src,   // [E]
    const int*   __restrict__ dst,   // [E]
    const float* __restrict__ b1,    // [64]
    const float* __restrict__ b2,    // [64]
    float*       __restrict__ out,   // [N,64]
    int E, int ntiles)
{
    extern __shared__ uint32_t smem[];

    const int tid  = threadIdx.x;
    const int lane = tid & 31;
    const int warp = tid >> 5;
    const int gr   = lane >> 2;
    const int gc   = lane & 3;
    const int wrow = warp * 32;
    const int gstride = gridDim.x;
    const unsigned FULL = 0xffffffffu;
    const bool odd = (gc & 1);
    const char* rbfB = (const char*)rbf;

    const uint32_t sbase = (uint32_t)__cvta_generic_to_shared(smem);

    // ---- weights (pre-converted fp16, verbatim padded layout), once ----
    for (int i = tid; i < 1088; i += THREADS)
        cp_async16(sbase + OFF_W1 * 4 + i * 16, (const char*)g_W1h + i * 16);
    for (int i = tid; i < 576; i += THREADS)
        cp_async16(sbase + OFF_W2 * 4 + i * 16, (const char*)g_W2h + i * 16);
    asm volatile("cp.async.commit_group;");

    // ---- B-fragment ldsm addresses ----
    const int lb = ((lane >> 4) << 3) | (lane & 7);
    const int sbyt = ((lane >> 3) & 1) * 16;
    uint32_t bW1a[4], bW2a[4];
    #pragma unroll
    for (int p = 0; p < 4; p++) {
        bW1a[p] = sbase + (OFF_W1 + (p * 16 + lb) * W1S) * 4 + sbyt;
        bW2a[p] = sbase + (OFF_W2 + (p * 16 + lb) * W2S) * 4 + sbyt;
    }

    // ---- per-lane A row byte-offsets (4 rows: gr, gr+8, gr+16, gr+24),
    //      includes the lane's column base 8*gc ----
    int tile = blockIdx.x;
    uint32_t rowoff[4], rowoffN[4];
    #pragma unroll
    for (int r = 0; r < 4; r++) {
        long e = (long)tile * BM + wrow + gr + 8 * r;
        long ec = (e < E) ? e : 0;
        rowoff[r] = (uint32_t)(ec * 512) + 8 * gc;
    }

    // ---- depth-4 rolling register buffer: Abuf[slot][row][seg] ----
    float2 Abuf[4][4][2];
    #pragma unroll
    for (int c = 0; c < 4; c++) {       // prologue: chunks 0..3 of first tile
        #pragma unroll
        for (int r = 0; r < 4; r++) {
            Abuf[c][r][0] = ldg_f2(rbfB + rowoff[r] + c * 64);
            Abuf[c][r][1] = ldg_f2(rbfB + rowoff[r] + c * 64 + 32);
        }
    }

    asm volatile("cp.async.wait_group 0;");
    __syncthreads();   // weights visible block-wide (only block barrier)

    for (; tile < ntiles; tile += gstride) {
        // next tile's row offsets (phantom reload of same tile at the end)
        {
            int tnext = tile + gstride;
            int tsrc = (tnext < ntiles) ? tnext : tile;
            #pragma unroll
            for (int r = 0; r < 4; r++) {
                long e = (long)tsrc * BM + wrow + gr + 8 * r;
                long ec = (e < E) ? e : 0;
                rowoffN[r] = (uint32_t)(ec * 512) + 8 * gc;
            }
        }

        // lane-private edge indices for this tile
        const long eMine = (long)tile * BM + wrow + lane;
        const bool valMine = (eMine < E);
        int myS = valMine ? src[eMine] : 0;
        int myD = valMine ? dst[eMine] : 0;

        // ---- GEMM1: 8 chunks of K=16; slot c&3 refilled with chunk c+4
        //      (current tile for c<4, NEXT tile's chunk c-4 for c>=4) ----
        float acc[2][8][4] = {};
        #pragma unroll
        for (int c = 0; c < 8; c++) {
            const int s = c & 3;
            uint32_t a[2][4];
            #pragma unroll
            for (int mt = 0; mt < 2; mt++) {
                a[mt][0] = pack_h2(Abuf[s][2 * mt + 0][0]);   // row gr(+16mt),   k=2gc
                a[mt][1] = pack_h2(Abuf[s][2 * mt + 1][0]);   // row gr+8(+16mt), k=2gc
                a[mt][2] = pack_h2(Abuf[s][2 * mt + 0][1]);   // k=2gc+8
                a[mt][3] = pack_h2(Abuf[s][2 * mt + 1][1]);
            }
            // refill slot (register WAR handled by scoreboard)
            if (c < 4) {
                #pragma unroll
                for (int r = 0; r < 4; r++) {
                    Abuf[s][r][0] = ldg_f2(rbfB + rowoff[r] + (c + 4) * 64);
                    Abuf[s][r][1] = ldg_f2(rbfB + rowoff[r] + (c + 4) * 64 + 32);
                }
            } else {
                #pragma unroll
                for (int r = 0; r < 4; r++) {
                    Abuf[s][r][0] = ldg_f2(rbfB + rowoffN[r] + (c - 4) * 64);
                    Abuf[s][r][1] = ldg_f2(rbfB + rowoffN[r] + (c - 4) * 64 + 32);
                }
            }
            #pragma unroll
            for (int p = 0; p < 4; p++) {
                uint32_t bb[4];
                ldsm_x4(bb, bW1a[p] + c * 32);
                mma_f16(acc[0][2 * p],     a[0], bb[0], bb[1]);
                mma_f16(acc[1][2 * p],     a[1], bb[0], bb[1]);
                mma_f16(acc[0][2 * p + 1], a[0], bb[2], bb[3]);
                mma_f16(acc[1][2 * p + 1], a[1], bb[2], bb[3]);
            }
        }
        // hand over row offsets (Abuf already holds next tile's chunks 0..3)
        #pragma unroll
        for (int r = 0; r < 4; r++) rowoff[r] = rowoffN[r];

        // ---- bias + softplus + pack: GEMM1 C-frags -> GEMM2 A-frags ----
        uint32_t hA[2][4][4];
        #pragma unroll
        for (int kt = 0; kt < 4; kt++) {
            float bA0 = __ldg(b1 + kt * 16 + 2 * gc);
            float bA1 = __ldg(b1 + kt * 16 + 2 * gc + 1);
            float bB0 = __ldg(b1 + kt * 16 + 8 + 2 * gc);
            float bB1 = __ldg(b1 + kt * 16 + 8 + 2 * gc + 1);
            #pragma unroll
            for (int mt = 0; mt < 2; mt++) {
                const float* cA = acc[mt][2 * kt];
                const float* cB = acc[mt][2 * kt + 1];
                hA[mt][kt][0] = pack_h2f(softplus_b05(cA[0] + bA0), softplus_b05(cA[1] + bA1));
                hA[mt][kt][1] = pack_h2f(softplus_b05(cA[2] + bA0), softplus_b05(cA[3] + bA1));
                hA[mt][kt][2] = pack_h2f(softplus_b05(cB[0] + bB0), softplus_b05(cB[1] + bB1));
                hA[mt][kt][3] = pack_h2f(softplus_b05(cB[2] + bB0), softplus_b05(cB[3] + bB1));
            }
        }

        // ---- GEMM2: K=64, 4 chunks of 16 ----
        float acc2[2][8][4] = {};
        #pragma unroll
        for (int kt = 0; kt < 4; kt++) {
            #pragma unroll
            for (int p = 0; p < 4; p++) {
                uint32_t bb[4];
                ldsm_x4(bb, bW2a[p] + kt * 32);
                mma_f16(acc2[0][2 * p],     hA[0][kt], bb[0], bb[1]);
                mma_f16(acc2[1][2 * p],     hA[1][kt], bb[0], bb[1]);
                mma_f16(acc2[0][2 * p + 1], hA[0][kt], bb[2], bb[3]);
                mma_f16(acc2[1][2 * p + 1], hA[1][kt], bb[2], bb[3]);
            }
        }

        // ---- epilogue: gate by nf[src], vector red scatter (next tile's A
        //      loads already in flight in registers) ----
        #pragma unroll
        for (int mt = 0; mt < 2; mt++) {
            int rowl = mt * 16 + gr + (odd ? 8 : 0);
            int s = __shfl_sync(FULL, myS, rowl);
            int d = __shfl_sync(FULL, myD, rowl);
            bool valid = ((long)tile * BM + wrow + rowl < E);
            const float* nfr = nf + (long)s * 64;
            float* outr = out + (long)d * 64;
            #pragma unroll
            for (int nt = 0; nt < 8; nt++) {
                float bc0 = __ldg(b2 + nt * 8 + 2 * gc);
                float bc1 = __ldg(b2 + nt * 8 + 2 * gc + 1);
                float g0 = acc2[mt][nt][0] + bc0, g1 = acc2[mt][nt][1] + bc1;
                float g2 = acc2[mt][nt][2] + bc0, g3 = acc2[mt][nt][3] + bc1;
                float x0 = __shfl_xor_sync(FULL, g0, 1);
                float x1 = __shfl_xor_sync(FULL, g1, 1);
                float x2 = __shfl_xor_sync(FULL, g2, 1);
                float x3 = __shfl_xor_sync(FULL, g3, 1);
                float v0, v1, v2, v3;
                if (odd) { v0 = x2; v1 = x3; v2 = g2; v3 = g3; }
                else     { v0 = g0; v1 = g1; v2 = x0; v3 = x1; }
                int col = nt * 8 + 4 * (gc >> 1);
                if (valid) {
                    float4 nf4 = *(const float4*)(nfr + col);
                    v0 *= nf4.x; v1 *= nf4.y; v2 *= nf4.z; v3 *= nf4.w;
                    asm volatile("red.global.add.v4.f32 [%0], {%1,%2,%3,%4};"
                                 :: "l"(outr + col), "f"(v0), "f"(v1), "f"(v2), "f"(v3)
                                 : "memory");
                }
            }
        }
    }
}

extern "C" void kernel_launch(void* const* d_in, const int* in_sizes, int n_in,
                              void* d_out, int out_size) {
    const float* rbf = (const float*)d_in[0];
    const float* nf  = (const float*)d_in[1];
    const int*   src = (const int*)d_in[2];
    const int*   dst = (const int*)d_in[3];
    const float* W1  = (const float*)d_in[4];
    const float* b1  = (const float*)d_in[5];
    const float* W2  = (const float*)d_in[6];
    const float* b2  = (const float*)d_in[7];
    float* out = (float*)d_out;

    const int E = in_sizes[2];
    const int ntiles = (E + BM - 1) / BM;

    cudaFuncSetAttribute(cfconv_f16_kernel,
                         cudaFuncAttributeMaxDynamicSharedMemorySize, SMEM_BYTES);

    int n4 = out_size / 4;
    setup_kernel<<<(n4 + 255) / 256, 256>>>((float4*)out, n4, W1, W2);

    int grid = 148 * 2;
    if (grid > ntiles) grid = ntiles;
    cfconv_f16_kernel<<<grid, THREADS, SMEM_BYTES>>>(
        rbf, nf, src, dst, b1, b2, out, E, ntiles);
}